// round 3
// baseline (speedup 1.0000x reference)
#include <cuda_runtime.h>
#include <math.h>
#include <stdint.h>

#define S_LEN 512
#define BATCH 64
#define HID 512
#define TAGS 50
#define K2 2500            // TAGS*TAGS
#define START_TAG 48
#define END_TAG 49
#define M_TOT (S_LEN*BATCH) // 32768

// Scratch (no allocations allowed): E = exp(scores), per-position target energy.
__device__ float g_E[(size_t)M_TOT * K2];   // ~327 MB
__device__ float g_tg[M_TOT];
__device__ int g_t64;   // target stored as int64 (vs int32)
__device__ int g_m32;   // mask stored as int32 (vs bool/byte)

// ---------------------------------------------------------------------------
// Kernel 0: zero output + detect input storage widths.
//   target: if int64, high 32-bit words are all 0 (values in [0,2500)).
//           if int32, odd words are random targets -> almost surely nonzero.
//   mask:   all-true mask. As bool bytes, words are 0x01010101 (> 1).
//           As int32, words are exactly 1.
// ---------------------------------------------------------------------------
__global__ void init_kernel(float* out, const void* target, const void* mask) {
    if (threadIdx.x == 0) {
        out[0] = 0.0f;
        const unsigned int* tw = (const unsigned int*)target;
        unsigned int nz = 0;
#pragma unroll
        for (int q = 0; q < 64; q++) nz |= tw[2 * q + 1];
        g_t64 = (nz == 0) ? 1 : 0;

        const unsigned int* mw = (const unsigned int*)mask;
        unsigned int big = 0;
#pragma unroll
        for (int q = 0; q < 64; q++) big |= (mw[q] > 1u) ? 1u : 0u;
        g_m32 = big ? 0 : 1;
    }
}

__device__ __forceinline__ bool mask_at(const void* mask, int idx) {
    if (g_m32) return ((const int*)mask)[idx] != 0;
    return ((const unsigned char*)mask)[idx] != 0;
}

// ---------------------------------------------------------------------------
// Kernel 1: scores = feats @ W^T + b, fused exp epilogue -> g_E
// A: [32768, 512] row-major (feats), W: [2500, 512] row-major.
// fp32 SIMT tiled GEMM, BM=BN=64, BK=16, 4x4 per thread, 256 threads.
// ---------------------------------------------------------------------------
#define BM 64
#define BN 64
#define BKK 16

__global__ __launch_bounds__(256) void gemm_exp_kernel(
    const float* __restrict__ A, const float* __restrict__ W,
    const float* __restrict__ bias)
{
    __shared__ float As[BKK][BM + 4];
    __shared__ float Bs[BKK][BN + 4];

    const int n0 = blockIdx.x * BN;
    const int m0 = blockIdx.y * BM;
    const int tid = threadIdx.x;

    const int lr = tid >> 2;          // 0..63  (row within tile)
    const int lc = (tid & 3) << 2;    // 0,4,8,12 (col within 16-wide k-tile)
    const int tm0 = (tid >> 4) << 2;
    const int tn0 = (tid & 15) << 2;

    float acc[4][4];
#pragma unroll
    for (int i = 0; i < 4; i++)
#pragma unroll
        for (int j = 0; j < 4; j++) acc[i][j] = 0.0f;

    const float* Arow = A + (size_t)(m0 + lr) * HID + lc;
    const bool bvalid = (n0 + lr) < K2;
    const float* Wrow = W + (size_t)(bvalid ? (n0 + lr) : 0) * HID + lc;

    for (int k0 = 0; k0 < HID; k0 += BKK) {
        float4 av = *(const float4*)(Arow + k0);
        float4 bv = make_float4(0.f, 0.f, 0.f, 0.f);
        if (bvalid) bv = *(const float4*)(Wrow + k0);
        As[lc + 0][lr] = av.x; As[lc + 1][lr] = av.y;
        As[lc + 2][lr] = av.z; As[lc + 3][lr] = av.w;
        Bs[lc + 0][lr] = bv.x; Bs[lc + 1][lr] = bv.y;
        Bs[lc + 2][lr] = bv.z; Bs[lc + 3][lr] = bv.w;
        __syncthreads();
#pragma unroll
        for (int kk = 0; kk < BKK; kk++) {
            float a0 = As[kk][tm0 + 0], a1 = As[kk][tm0 + 1];
            float a2 = As[kk][tm0 + 2], a3 = As[kk][tm0 + 3];
            float b0 = Bs[kk][tn0 + 0], b1 = Bs[kk][tn0 + 1];
            float b2 = Bs[kk][tn0 + 2], b3 = Bs[kk][tn0 + 3];
            acc[0][0] = fmaf(a0, b0, acc[0][0]); acc[0][1] = fmaf(a0, b1, acc[0][1]);
            acc[0][2] = fmaf(a0, b2, acc[0][2]); acc[0][3] = fmaf(a0, b3, acc[0][3]);
            acc[1][0] = fmaf(a1, b0, acc[1][0]); acc[1][1] = fmaf(a1, b1, acc[1][1]);
            acc[1][2] = fmaf(a1, b2, acc[1][2]); acc[1][3] = fmaf(a1, b3, acc[1][3]);
            acc[2][0] = fmaf(a2, b0, acc[2][0]); acc[2][1] = fmaf(a2, b1, acc[2][1]);
            acc[2][2] = fmaf(a2, b2, acc[2][2]); acc[2][3] = fmaf(a2, b3, acc[2][3]);
            acc[3][0] = fmaf(a3, b0, acc[3][0]); acc[3][1] = fmaf(a3, b1, acc[3][1]);
            acc[3][2] = fmaf(a3, b2, acc[3][2]); acc[3][3] = fmaf(a3, b3, acc[3][3]);
        }
        __syncthreads();
    }

    // epilogue: E = exp(score + bias)
#pragma unroll
    for (int i = 0; i < 4; i++) {
        size_t row = (size_t)(m0 + tm0 + i) * K2;
#pragma unroll
        for (int j = 0; j < 4; j++) {
            int n = n0 + tn0 + j;
            if (n < K2)
                g_E[row + n] = __expf(acc[i][j] + __ldg(&bias[n]));
        }
    }
}

// ---------------------------------------------------------------------------
// Kernel 2: per-position target energy: g_tg[m] = mask[m] ? dot(feats[m], W[t]) + b[t] : 0
// One warp per position.
// ---------------------------------------------------------------------------
__global__ __launch_bounds__(256) void tg_kernel(
    const float* __restrict__ feats, const float* __restrict__ W,
    const float* __restrict__ bias, const void* __restrict__ target,
    const void* __restrict__ mask)
{
    const int warp = (blockIdx.x * blockDim.x + threadIdx.x) >> 5;
    const int lane = threadIdx.x & 31;
    if (warp >= M_TOT) return;

    long long t;
    if (g_t64) t = ((const long long*)target)[warp];
    else       t = (long long)((const int*)target)[warp];

    const float4* a  = (const float4*)(feats + (size_t)warp * HID);
    const float4* w4 = (const float4*)(W + (size_t)t * HID);
    float s = 0.0f;
#pragma unroll
    for (int u = 0; u < 4; u++) {
        float4 av = a[lane + u * 32];
        float4 wv = w4[lane + u * 32];
        s += av.x * wv.x + av.y * wv.y + av.z * wv.z + av.w * wv.w;
    }
#pragma unroll
    for (int off = 16; off; off >>= 1) s += __shfl_xor_sync(0xffffffffu, s, off);
    if (lane == 0)
        g_tg[warp] = mask_at(mask, warp) ? (s + bias[t]) : 0.0f;
}

// ---------------------------------------------------------------------------
// Kernel 3: sequential forward scan, one block per batch element.
// Step: new[j] = log( sum_i E[s,b,i,j] * exp(p[i]-c) ) + c
// E tiles (10 KB/step) are double-buffered into SMEM via cp.async.
// Epilogue: out += (p[END_TAG] - sum_s g_tg[s,b]) / BATCH
// ---------------------------------------------------------------------------
__device__ __forceinline__ void cp_async16(void* smem_dst, const void* gmem_src) {
    unsigned int d = (unsigned int)__cvta_generic_to_shared(smem_dst);
    asm volatile("cp.async.cg.shared.global [%0], [%1], 16;" :: "r"(d), "l"(gmem_src) : "memory");
}
__device__ __forceinline__ void cp_async_commit() {
    asm volatile("cp.async.commit_group;" ::: "memory");
}

__global__ __launch_bounds__(128) void scan_kernel(
    const void* __restrict__ mask, float* __restrict__ out)
{
    __shared__ __align__(16) float Es[2][K2];
    __shared__ float p[TAGS];
    __shared__ float pe[TAGS];
    __shared__ float cmax;
    __shared__ float red[4];

    const int b = blockIdx.x;
    const int tid = threadIdx.x;

    // partition0 = scores4[0, b, START_TAG, :] = log(E)
    if (tid < TAGS)
        p[tid] = __logf(g_E[(size_t)b * K2 + START_TAG * TAGS + tid]);

    // prefetch tile for s = 1
    {
        const float4* src = (const float4*)(g_E + (size_t)(1 * BATCH + b) * K2);
        for (int t = tid; t < K2 / 4; t += 128)
            cp_async16(&Es[1][t * 4], src + t);
        cp_async_commit();
    }

    for (int s = 1; s < S_LEN; s++) {
        const int cur = s & 1;
        if (s + 1 < S_LEN) {
            const float4* src = (const float4*)(g_E + (size_t)((s + 1) * BATCH + b) * K2);
            for (int t = tid; t < K2 / 4; t += 128)
                cp_async16(&Es[cur ^ 1][t * 4], src + t);
            cp_async_commit();
            asm volatile("cp.async.wait_group 1;" ::: "memory");
        } else {
            asm volatile("cp.async.wait_group 0;" ::: "memory");
        }
        __syncthreads();

        // c = max_i p[i]
        if (tid < 32) {
            float v = p[tid];
            if (tid + 32 < TAGS) v = fmaxf(v, p[tid + 32]);
#pragma unroll
            for (int off = 16; off; off >>= 1)
                v = fmaxf(v, __shfl_xor_sync(0xffffffffu, v, off));
            if (tid == 0) cmax = v;
        }
        __syncthreads();
        if (tid < TAGS) pe[tid] = __expf(p[tid] - cmax);
        __syncthreads();

        float newp = 0.0f;
        if (tid < TAGS) {
            float acc = 0.0f;
            const float* E = Es[cur];
#pragma unroll
            for (int i = 0; i < TAGS; i++)
                acc = fmaf(E[i * TAGS + tid], pe[i], acc);
            newp = __logf(acc) + cmax;
        }
        const bool m = mask_at(mask, s * BATCH + b);
        __syncthreads();
        if (tid < TAGS && m) p[tid] = newp;
        __syncthreads();
    }

    // epilogue: subtract this batch's target energy, accumulate loss
    float tg = 0.0f;
    for (int s = tid; s < S_LEN; s += 128) tg += g_tg[s * BATCH + b];
#pragma unroll
    for (int off = 16; off; off >>= 1) tg += __shfl_xor_sync(0xffffffffu, tg, off);
    if ((tid & 31) == 0) red[tid >> 5] = tg;
    __syncthreads();
    if (tid == 0) {
        float tgb = red[0] + red[1] + red[2] + red[3];
        atomicAdd(out, (p[END_TAG] - tgb) / (float)BATCH);
    }
}

// ---------------------------------------------------------------------------
extern "C" void kernel_launch(void* const* d_in, const int* in_sizes, int n_in,
                              void* d_out, int out_size)
{
    const float* feats  = (const float*)d_in[0];
    const float* W      = (const float*)d_in[1];
    const float* bias   = (const float*)d_in[2];
    const void*  target = d_in[3];
    const void*  mask   = (const void*)d_in[4];
    float* out = (float*)d_out;

    init_kernel<<<1, 32>>>(out, target, mask);

    dim3 ggrid((K2 + BN - 1) / BN, M_TOT / BM);   // 40 x 512
    gemm_exp_kernel<<<ggrid, 256>>>(feats, W, bias);

    tg_kernel<<<M_TOT / 8, 256>>>(feats, W, bias, target, mask);

    scan_kernel<<<BATCH, 128>>>(mask, out);
}

// round 5
// speedup vs baseline: 3.7512x; 3.7512x over previous
#include <cuda_runtime.h>
#include <math.h>
#include <stdint.h>

#define S_LEN 512
#define BATCH 64
#define HID 512
#define TAGS 50
#define K2 2500            // TAGS*TAGS
#define K2P 2512           // padded row (10048 B, 16B-aligned for bulk copy)
#define START_TAG 48
#define END_TAG 49
#define M_TOT (S_LEN*BATCH) // 32768

// Scratch (no allocations allowed)
__device__ __align__(1024) float g_E[(size_t)M_TOT * K2P];   // ~329 MB
__device__ __align__(16) float g_A[(size_t)M_TOT * HID];     // tf32-rounded feats
__device__ __align__(16) float g_W[(size_t)K2 * HID];        // tf32-rounded W
__device__ float g_tg[M_TOT];
__device__ int g_t64;   // target stored as int64 (vs int32)
__device__ int g_m32;   // mask stored as int32 (vs bool/byte)

// ===========================================================================
// PTX helpers
// ===========================================================================
__device__ __forceinline__ uint32_t smem_u32(const void* p) {
    uint32_t a;
    asm("{ .reg .u64 t; cvta.to.shared.u64 t, %1; cvt.u32.u64 %0, t; }" : "=r"(a) : "l"(p));
    return a;
}
#define MBAR_INIT(addr, cnt) \
    asm volatile("mbarrier.init.shared.b64 [%0], %1;" :: "r"(addr), "r"(cnt) : "memory")
#define MBAR_EXPECT_TX(addr, bytes) \
    asm volatile("mbarrier.arrive.expect_tx.shared.b64 _, [%0], %1;" :: "r"(addr), "r"(bytes) : "memory")
#define MBAR_WAIT(addr, par) do {                                              \
    uint32_t _m = (addr), _p = (par), _d;                                      \
    asm volatile("{\n\t.reg .pred p;\n\t"                                      \
        "mbarrier.try_wait.parity.acquire.cta.shared::cta.b64 p, [%1], %2;\n\t"\
        "selp.b32 %0, 1, 0, p;\n\t}" : "=r"(_d) : "r"(_m), "r"(_p) : "memory");\
    if (!_d) {                                                                 \
        asm volatile("{\n\t.reg .pred P1;\n\t"                                 \
            "W%=:\n\t"                                                         \
            "mbarrier.try_wait.parity.acquire.cta.shared::cta.b64 P1, [%0], %1, 0x989680;\n\t" \
            "@P1 bra.uni D%=;\n\t"                                             \
            "bra.uni W%=;\n\t"                                                 \
            "D%=:\n\t}" :: "r"(_m), "r"(_p) : "memory");                       \
    }                                                                          \
} while (0)
__device__ __forceinline__ void cp16(uint32_t dst, const void* src) {
    asm volatile("cp.async.cg.shared.global [%0], [%1], 16;" :: "r"(dst), "l"(src) : "memory");
}
__device__ __forceinline__ float tf32_rna(float x) {
    uint32_t r;
    asm("cvt.rna.tf32.f32 %0, %1;" : "=r"(r) : "f"(x));
    return __uint_as_float(r);
}
__device__ __forceinline__ void mma_tf32(float& d0, float& d1, float& d2, float& d3,
                                         uint32_t a0, uint32_t a1, uint32_t a2, uint32_t a3,
                                         uint32_t b0, uint32_t b1) {
    asm volatile(
        "mma.sync.aligned.m16n8k8.row.col.f32.tf32.tf32.f32 "
        "{%0,%1,%2,%3},{%4,%5,%6,%7},{%8,%9},{%0,%1,%2,%3};"
        : "+f"(d0), "+f"(d1), "+f"(d2), "+f"(d3)
        : "r"(a0), "r"(a1), "r"(a2), "r"(a3), "r"(b0), "r"(b1));
}

// ===========================================================================
// Kernel 0: zero output + detect input storage widths
// ===========================================================================
__global__ void init_kernel(float* out, const void* target, const void* mask) {
    if (threadIdx.x == 0) {
        out[0] = 0.0f;
        const unsigned int* tw = (const unsigned int*)target;
        unsigned int nz = 0;
#pragma unroll
        for (int q = 0; q < 64; q++) nz |= tw[2 * q + 1];
        g_t64 = (nz == 0) ? 1 : 0;
        const unsigned int* mw = (const unsigned int*)mask;
        unsigned int big = 0;
#pragma unroll
        for (int q = 0; q < 64; q++) big |= (mw[q] > 1u) ? 1u : 0u;
        g_m32 = big ? 0 : 1;
    }
}
__device__ __forceinline__ bool mask_at(const void* mask, int idx) {
    if (g_m32) return ((const int*)mask)[idx] != 0;
    return ((const unsigned char*)mask)[idx] != 0;
}

// ===========================================================================
// Kernel 0b: round feats/W to tf32 (RN) once, off the GEMM inner loop
// ===========================================================================
__global__ __launch_bounds__(256) void cvt_kernel(
    const float* __restrict__ A, const float* __restrict__ W)
{
    const int stride = gridDim.x * blockDim.x;
    int i = blockIdx.x * blockDim.x + threadIdx.x;
    for (; i < M_TOT * HID; i += stride) g_A[i] = tf32_rna(A[i]);
    for (i -= M_TOT * HID; i < K2 * HID; i += stride) g_W[i] = tf32_rna(W[i]);
}

// ===========================================================================
// Kernel 1: tf32 mma.sync GEMM + exp epilogue -> g_E
// BM=256, BN=128, BK=32. 512 threads, warp grid 4(m)x4(n), warp tile 64x32.
// k-permuted fragments: slot {t, t+4} <- physical k {2t, 2t+1} on BOTH A and B
// (k-permutation invariant), so every fragment load is one LDS.64.
// ===========================================================================
#define BM 256
#define BN 128
#define BKF 32
#define NCHUNK (HID / BKF)
#define RPADF 36                         // row stride in floats (144B, 16B mult)
#define ABYTES (BM * RPADF * 4)          // 36864
#define BBYTES (BN * RPADF * 4)          // 18432
#define BUFSZ  (ABYTES + BBYTES)         // 55296
#define GEMM_SMEM (2 * BUFSZ + 512)

__global__ __launch_bounds__(512) void gemm_tc_kernel(const float* __restrict__ bias)
{
    extern __shared__ char smem[];
    const uint32_t sbase = smem_u32(smem);
    const int tid = threadIdx.x;
    const int n0 = blockIdx.x * BN;
    const int m0 = blockIdx.y * BM;
    float* sbias = (float*)(smem + 2 * BUFSZ);

    {   // bias tile
        if (tid < BN) {
            int n = n0 + tid;
            sbias[tid] = (n < K2) ? bias[n] : 0.0f;
        }
    }

    // cp.async fill of one chunk into buffer `buf`
    auto fill = [&](int c, int buf) {
        const int k0 = c * BKF;
        const uint32_t ab = sbase + buf * BUFSZ;
        const uint32_t bb = ab + ABYTES;
        // A: 256 rows x 8 segs of 16B = 2048 units
#pragma unroll
        for (int i = 0; i < 4; i++) {
            int u = tid + i * 512;
            int r = u >> 3, seg = u & 7;
            cp16(ab + r * (RPADF * 4) + seg * 16,
                 g_A + (size_t)(m0 + r) * HID + k0 + seg * 4);
        }
        // B: 128 rows x 8 segs = 1024 units
#pragma unroll
        for (int i = 0; i < 2; i++) {
            int u = tid + i * 512;
            int r = u >> 3, seg = u & 7;
            int n = n0 + r; if (n >= K2) n = K2 - 1;
            cp16(bb + r * (RPADF * 4) + seg * 16,
                 g_W + (size_t)n * HID + k0 + seg * 4);
        }
        asm volatile("cp.async.commit_group;" ::: "memory");
    };

    const int w = tid >> 5;
    const int lane = tid & 31;
    const int g = lane >> 2;       // groupID
    const int t = lane & 3;        // thread-in-group
    const int wm = w >> 2;         // 0..3 -> m offset wm*64
    const int wn = w & 3;          // 0..3 -> n offset wn*32

    float acc[4][4][4];            // [m-tile][n-tile][frag]
#pragma unroll
    for (int i = 0; i < 4; i++)
#pragma unroll
        for (int j = 0; j < 4; j++)
#pragma unroll
            for (int q = 0; q < 4; q++) acc[i][j][q] = 0.0f;

    fill(0, 0);

    for (int c = 0; c < NCHUNK; c++) {
        if (c + 1 < NCHUNK) {
            fill(c + 1, (c + 1) & 1);
            asm volatile("cp.async.wait_group 1;" ::: "memory");
        } else {
            asm volatile("cp.async.wait_group 0;" ::: "memory");
        }
        __syncthreads();

        const float* sA = (const float*)(smem + (c & 1) * BUFSZ);
        const float* sB = (const float*)(smem + (c & 1) * BUFSZ + ABYTES);

#pragma unroll
        for (int j = 0; j < 4; j++) {
            const int cb = j * 8 + 2 * t;      // physical k pair for this thread
            uint32_t af[4][4];
#pragma unroll
            for (int i = 0; i < 4; i++) {
                const int ra = wm * 64 + i * 16 + g;
                float2 lo = *(const float2*)&sA[ra * RPADF + cb];
                float2 hi = *(const float2*)&sA[(ra + 8) * RPADF + cb];
                af[i][0] = __float_as_uint(lo.x);
                af[i][1] = __float_as_uint(hi.x);
                af[i][2] = __float_as_uint(lo.y);
                af[i][3] = __float_as_uint(hi.y);
            }
            uint32_t bf[4][2];
#pragma unroll
            for (int nt = 0; nt < 4; nt++) {
                const int rb = wn * 32 + nt * 8 + g;
                float2 bv = *(const float2*)&sB[rb * RPADF + cb];
                bf[nt][0] = __float_as_uint(bv.x);
                bf[nt][1] = __float_as_uint(bv.y);
            }
#pragma unroll
            for (int i = 0; i < 4; i++)
#pragma unroll
                for (int nt = 0; nt < 4; nt++)
                    mma_tf32(acc[i][nt][0], acc[i][nt][1], acc[i][nt][2], acc[i][nt][3],
                             af[i][0], af[i][1], af[i][2], af[i][3],
                             bf[nt][0], bf[nt][1]);
        }
        __syncthreads();
    }

    // epilogue: E = exp(D + bias); d0,d1 -> (row g, cols 2t,2t+1), d2,d3 -> row g+8
#pragma unroll
    for (int i = 0; i < 4; i++) {
        const int r0 = m0 + wm * 64 + i * 16 + g;
#pragma unroll
        for (int nt = 0; nt < 4; nt++) {
            const int cloc = wn * 32 + nt * 8 + 2 * t;
            const int cg = n0 + cloc;
            if (cg < K2) {
                const float bz0 = sbias[cloc], bz1 = sbias[cloc + 1];
                float2 v0, v1;
                v0.x = __expf(acc[i][nt][0] + bz0);
                v0.y = __expf(acc[i][nt][1] + bz1);
                v1.x = __expf(acc[i][nt][2] + bz0);
                v1.y = __expf(acc[i][nt][3] + bz1);
                *(float2*)(g_E + (size_t)r0 * K2P + cg) = v0;
                *(float2*)(g_E + (size_t)(r0 + 8) * K2P + cg) = v1;
            }
        }
    }
}

// ===========================================================================
// Kernel 2: per-position target energy (one warp per position)
// ===========================================================================
__global__ __launch_bounds__(256) void tg_kernel(
    const float* __restrict__ feats, const float* __restrict__ W,
    const float* __restrict__ bias, const void* __restrict__ target,
    const void* __restrict__ mask)
{
    const int warp = (blockIdx.x * blockDim.x + threadIdx.x) >> 5;
    const int lane = threadIdx.x & 31;
    if (warp >= M_TOT) return;

    long long t;
    if (g_t64) t = ((const long long*)target)[warp];
    else       t = (long long)((const int*)target)[warp];

    const float4* a  = (const float4*)(feats + (size_t)warp * HID);
    const float4* w4 = (const float4*)(W + (size_t)t * HID);
    float s = 0.0f;
#pragma unroll
    for (int u = 0; u < 4; u++) {
        float4 av = a[lane + u * 32];
        float4 wv = w4[lane + u * 32];
        s += av.x * wv.x + av.y * wv.y + av.z * wv.z + av.w * wv.w;
    }
#pragma unroll
    for (int off = 16; off; off >>= 1) s += __shfl_xor_sync(0xffffffffu, s, off);
    if (lane == 0)
        g_tg[warp] = mask_at(mask, warp) ? (s + bias[t]) : 0.0f;
}

// ===========================================================================
// Kernel 3: sequential forward scan, one block per batch element.
// E tiles fetched with single cp.async.bulk per step, 4-deep ring, prefetch 3.
// ===========================================================================
__global__ __launch_bounds__(128) void scan_kernel(
    const void* __restrict__ mask, float* __restrict__ out)
{
    __shared__ __align__(16) float Es[4][K2P];
    __shared__ __align__(8) unsigned long long mbar[4];
    __shared__ float p[TAGS];
    __shared__ float pe[TAGS];
    __shared__ float cmax;
    __shared__ float red[4];

    const int b = blockIdx.x;
    const int tid = threadIdx.x;
    const uint32_t mb = smem_u32(mbar);
    const uint32_t esb = smem_u32(Es);

    if (tid == 0) {
#pragma unroll
        for (int q = 0; q < 4; q++) MBAR_INIT(mb + 8 * q, 1);
    }
    if (tid < TAGS)
        p[tid] = __logf(g_E[(size_t)b * K2P + START_TAG * TAGS + tid]);
    __syncthreads();

    if (tid == 0) {
#pragma unroll
        for (int t = 1; t <= 3; t++) {
            int st = (t - 1) & 3;
            MBAR_EXPECT_TX(mb + 8 * st, K2P * 4);
            asm volatile(
                "cp.async.bulk.shared::cta.global.mbarrier::complete_tx::bytes [%0], [%1], %2, [%3];"
                :: "r"(esb + st * (K2P * 4)),
                   "l"(g_E + (size_t)(t * BATCH + b) * K2P),
                   "r"(K2P * 4), "r"(mb + 8 * st) : "memory");
        }
    }

    for (int s = 1; s < S_LEN; s++) {
        const int st = (s - 1) & 3;
        if (tid == 0 && s + 3 < S_LEN) {
            int ps = (s + 2) & 3;
            MBAR_EXPECT_TX(mb + 8 * ps, K2P * 4);
            asm volatile(
                "cp.async.bulk.shared::cta.global.mbarrier::complete_tx::bytes [%0], [%1], %2, [%3];"
                :: "r"(esb + ps * (K2P * 4)),
                   "l"(g_E + (size_t)((s + 3) * BATCH + b) * K2P),
                   "r"(K2P * 4), "r"(mb + 8 * ps) : "memory");
        }
        MBAR_WAIT(mb + 8 * st, ((s - 1) >> 2) & 1);

        if (tid < 32) {
            float v = p[tid];
            if (tid + 32 < TAGS) v = fmaxf(v, p[tid + 32]);
#pragma unroll
            for (int off = 16; off; off >>= 1)
                v = fmaxf(v, __shfl_xor_sync(0xffffffffu, v, off));
            if (tid == 0) cmax = v;
        }
        __syncthreads();
        if (tid < TAGS) pe[tid] = __expf(p[tid] - cmax);
        __syncthreads();

        float newp = 0.0f;
        if (tid < TAGS) {
            float a = 0.0f;
            const float* E = Es[st];
#pragma unroll
            for (int i = 0; i < TAGS; i++)
                a = fmaf(E[i * TAGS + tid], pe[i], a);
            newp = __logf(a) + cmax;
        }
        const bool m = mask_at(mask, s * BATCH + b);
        __syncthreads();
        if (tid < TAGS && m) p[tid] = newp;
        __syncthreads();
    }

    float tg = 0.0f;
    for (int s = tid; s < S_LEN; s += 128) tg += g_tg[s * BATCH + b];
#pragma unroll
    for (int off = 16; off; off >>= 1) tg += __shfl_xor_sync(0xffffffffu, tg, off);
    if ((tid & 31) == 0) red[tid >> 5] = tg;
    __syncthreads();
    if (tid == 0) {
        float tgb = red[0] + red[1] + red[2] + red[3];
        atomicAdd(out, (p[END_TAG] - tgb) / (float)BATCH);
    }
}

// ===========================================================================
extern "C" void kernel_launch(void* const* d_in, const int* in_sizes, int n_in,
                              void* d_out, int out_size)
{
    const float* feats  = (const float*)d_in[0];
    const float* W      = (const float*)d_in[1];
    const float* bias   = (const float*)d_in[2];
    const void*  target = d_in[3];
    const void*  mask   = (const void*)d_in[4];
    float* out = (float*)d_out;

    cudaFuncSetAttribute(gemm_tc_kernel,
                         cudaFuncAttributeMaxDynamicSharedMemorySize, GEMM_SMEM);

    init_kernel<<<1, 32>>>(out, target, mask);
    cvt_kernel<<<592, 256>>>(feats, W);

    dim3 ggrid((K2 + BN - 1) / BN, M_TOT / BM);   // 20 x 128
    gemm_tc_kernel<<<ggrid, 512, GEMM_SMEM>>>(bias);

    tg_kernel<<<M_TOT / 8, 256>>>(feats, W, bias, target, mask);

    scan_kernel<<<BATCH, 128>>>(mask, out);
}

// round 7
// speedup vs baseline: 6.7525x; 1.8001x over previous
#include <cuda_runtime.h>
#include <cuda_bf16.h>
#include <math.h>
#include <stdint.h>

#define S_LEN 512
#define BATCH 64
#define HID 512
#define TAGS 50
#define K2 2500            // TAGS*TAGS
#define K2P 2512           // padded row (10048 B, 16B-aligned for bulk copy)
#define START_TAG 48
#define END_TAG 49
#define M_TOT (S_LEN*BATCH) // 32768

// Scratch (no allocations allowed)
__device__ __align__(1024) float g_E[(size_t)M_TOT * K2P];     // ~329 MB
__device__ __align__(16) unsigned int g_Ah[(size_t)M_TOT * HID / 2];  // bf16 feats
__device__ __align__(16) unsigned int g_Wh[(size_t)K2 * HID / 2];     // bf16 W
__device__ float g_tg[M_TOT];
__device__ int g_t64;   // target stored as int64 (vs int32)
__device__ int g_m32;   // mask stored as int32 (vs bool/byte)

// ===========================================================================
// PTX helpers
// ===========================================================================
__device__ __forceinline__ uint32_t smem_u32(const void* p) {
    uint32_t a;
    asm("{ .reg .u64 t; cvta.to.shared.u64 t, %1; cvt.u32.u64 %0, t; }" : "=r"(a) : "l"(p));
    return a;
}
#define MBAR_INIT(addr, cnt) \
    asm volatile("mbarrier.init.shared.b64 [%0], %1;" :: "r"(addr), "r"(cnt) : "memory")
#define MBAR_EXPECT_TX(addr, bytes) \
    asm volatile("mbarrier.arrive.expect_tx.shared.b64 _, [%0], %1;" :: "r"(addr), "r"(bytes) : "memory")
#define MBAR_WAIT(addr, par) do {                                              \
    uint32_t _m = (addr), _p = (par), _d;                                      \
    asm volatile("{\n\t.reg .pred p;\n\t"                                      \
        "mbarrier.try_wait.parity.acquire.cta.shared::cta.b64 p, [%1], %2;\n\t"\
        "selp.b32 %0, 1, 0, p;\n\t}" : "=r"(_d) : "r"(_m), "r"(_p) : "memory");\
    if (!_d) {                                                                 \
        asm volatile("{\n\t.reg .pred P1;\n\t"                                 \
            "W%=:\n\t"                                                         \
            "mbarrier.try_wait.parity.acquire.cta.shared::cta.b64 P1, [%0], %1, 0x989680;\n\t" \
            "@P1 bra.uni D%=;\n\t"                                             \
            "bra.uni W%=;\n\t"                                                 \
            "D%=:\n\t}" :: "r"(_m), "r"(_p) : "memory");                       \
    }                                                                          \
} while (0)
__device__ __forceinline__ void cp16(uint32_t dst, const void* src) {
    asm volatile("cp.async.cg.shared.global [%0], [%1], 16;" :: "r"(dst), "l"(src) : "memory");
}
__device__ __forceinline__ uint32_t pack_bf16x2(float lo, float hi) {
    uint32_t r;
    asm("cvt.rn.bf16x2.f32 %0, %1, %2;" : "=r"(r) : "f"(hi), "f"(lo));
    return r;
}
__device__ __forceinline__ void mma_bf16(float& d0, float& d1, float& d2, float& d3,
                                         uint32_t a0, uint32_t a1, uint32_t a2, uint32_t a3,
                                         uint32_t b0, uint32_t b1) {
    asm volatile(
        "mma.sync.aligned.m16n8k16.row.col.f32.bf16.bf16.f32 "
        "{%0,%1,%2,%3},{%4,%5,%6,%7},{%8,%9},{%0,%1,%2,%3};"
        : "+f"(d0), "+f"(d1), "+f"(d2), "+f"(d3)
        : "r"(a0), "r"(a1), "r"(a2), "r"(a3), "r"(b0), "r"(b1));
}

// ===========================================================================
// Kernel 0: zero output + detect input storage widths
// ===========================================================================
__global__ void init_kernel(float* out, const void* target, const void* mask) {
    if (threadIdx.x == 0) {
        out[0] = 0.0f;
        const unsigned int* tw = (const unsigned int*)target;
        unsigned int nz = 0;
#pragma unroll
        for (int q = 0; q < 64; q++) nz |= tw[2 * q + 1];
        g_t64 = (nz == 0) ? 1 : 0;
        const unsigned int* mw = (const unsigned int*)mask;
        unsigned int big = 0;
#pragma unroll
        for (int q = 0; q < 64; q++) big |= (mw[q] > 1u) ? 1u : 0u;
        g_m32 = big ? 0 : 1;
    }
}
__device__ __forceinline__ bool mask_at(const void* mask, int idx) {
    if (g_m32) return ((const int*)mask)[idx] != 0;
    return ((const unsigned char*)mask)[idx] != 0;
}

// ===========================================================================
// Kernel 0b: convert feats/W to bf16 (RN) once
// ===========================================================================
__global__ __launch_bounds__(256) void cvt_kernel(
    const float* __restrict__ A, const float* __restrict__ W)
{
    const int NA = M_TOT * HID / 2;
    const int NW = K2 * HID / 2;
    const int stride = gridDim.x * blockDim.x;
    for (int i = blockIdx.x * blockDim.x + threadIdx.x; i < NA; i += stride) {
        float2 v = ((const float2*)A)[i];
        g_Ah[i] = pack_bf16x2(v.x, v.y);
    }
    for (int i = blockIdx.x * blockDim.x + threadIdx.x; i < NW; i += stride) {
        float2 v = ((const float2*)W)[i];
        g_Wh[i] = pack_bf16x2(v.x, v.y);
    }
}

// ===========================================================================
// Kernel 1: bf16 mma.sync GEMM + exp epilogue -> g_E
// BM=BN=128, BK=32. 256 threads, warp grid 2(m)x4(n), warp tile 64x32.
// k-permuted fragments (same permutation on A and B): each fragment pair is
// one LDS.64 of 4 contiguous bf16.
// ===========================================================================
#define BM 128
#define BN 128
#define BKF 32                    // k per chunk (bf16 elems)
#define NCHUNK (HID / BKF)        // 16
#define RPADB 80                  // row stride bytes (64B data + 16B pad)
#define ABYTES (BM * RPADB)       // 10240
#define BBYTES (BN * RPADB)       // 10240
#define BUFSZ  (ABYTES + BBYTES)  // 20480
#define GEMM_SMEM (2 * BUFSZ + 512)

__global__ __launch_bounds__(256, 2) void gemm_tc_kernel(const float* __restrict__ bias)
{
    extern __shared__ char smem[];
    const uint32_t sbase = smem_u32(smem);
    const int tid = threadIdx.x;
    const int n0 = blockIdx.x * BN;
    const int m0 = blockIdx.y * BM;
    float* sbias = (float*)(smem + 2 * BUFSZ);

    if (tid < BN) {
        int n = n0 + tid;
        sbias[tid] = (n < K2) ? bias[n] : 0.0f;
    }

    // cp.async fill of one 32-k chunk into buffer `buf`
    auto fill = [&](int c, int buf) {
        const int k0h = c * BKF;          // in halfs
        const uint32_t ab = sbase + buf * BUFSZ;
        const uint32_t bb = ab + ABYTES;
        // A: 128 rows x 4 segs of 16B = 512 units
#pragma unroll
        for (int i = 0; i < 2; i++) {
            int u = tid + i * 256;
            int r = u >> 2, seg = u & 3;
            cp16(ab + r * RPADB + seg * 16,
                 g_Ah + ((size_t)(m0 + r) * HID + k0h) / 2 + seg * 4);
        }
        // B: 128 rows x 4 segs = 512 units
#pragma unroll
        for (int i = 0; i < 2; i++) {
            int u = tid + i * 256;
            int r = u >> 2, seg = u & 3;
            int n = n0 + r; if (n >= K2) n = K2 - 1;
            cp16(bb + r * RPADB + seg * 16,
                 g_Wh + ((size_t)n * HID + k0h) / 2 + seg * 4);
        }
        asm volatile("cp.async.commit_group;" ::: "memory");
    };

    const int w = tid >> 5;
    const int lane = tid & 31;
    const int g = lane >> 2;       // groupID (row within 8)
    const int t = lane & 3;        // thread-in-group
    const int wm = w >> 2;         // 0..1 -> m offset wm*64
    const int wn = w & 3;          // 0..3 -> n offset wn*32

    float acc[4][4][4];
#pragma unroll
    for (int i = 0; i < 4; i++)
#pragma unroll
        for (int j = 0; j < 4; j++)
#pragma unroll
            for (int q = 0; q < 4; q++) acc[i][j][q] = 0.0f;

    fill(0, 0);

    for (int c = 0; c < NCHUNK; c++) {
        if (c + 1 < NCHUNK) {
            fill(c + 1, (c + 1) & 1);
            asm volatile("cp.async.wait_group 1;" ::: "memory");
        } else {
            asm volatile("cp.async.wait_group 0;" ::: "memory");
        }
        __syncthreads();

        const char* sA = smem + (c & 1) * BUFSZ;
        const char* sB = sA + ABYTES;

#pragma unroll
        for (int j = 0; j < 2; j++) {            // two k16 steps per chunk
            const int koff = j * 32 + 8 * t;     // byte offset in row
            uint2 af[4][2];
#pragma unroll
            for (int i = 0; i < 4; i++) {
                const int ra = wm * 64 + i * 16 + g;
                af[i][0] = *(const uint2*)(sA + ra * RPADB + koff);
                af[i][1] = *(const uint2*)(sA + (ra + 8) * RPADB + koff);
            }
            uint2 bf[4];
#pragma unroll
            for (int nt = 0; nt < 4; nt++) {
                const int rb = wn * 32 + nt * 8 + g;
                bf[nt] = *(const uint2*)(sB + rb * RPADB + koff);
            }
#pragma unroll
            for (int i = 0; i < 4; i++)
#pragma unroll
                for (int nt = 0; nt < 4; nt++)
                    mma_bf16(acc[i][nt][0], acc[i][nt][1], acc[i][nt][2], acc[i][nt][3],
                             af[i][0].x, af[i][1].x, af[i][0].y, af[i][1].y,
                             bf[nt].x, bf[nt].y);
        }
        __syncthreads();
    }

    // epilogue: E = exp(D + bias); d0,d1 -> (row g, cols 2t,2t+1), d2,d3 -> row g+8
#pragma unroll
    for (int i = 0; i < 4; i++) {
        const int r0 = m0 + wm * 64 + i * 16 + g;
#pragma unroll
        for (int nt = 0; nt < 4; nt++) {
            const int cloc = wn * 32 + nt * 8 + 2 * t;
            const int cg = n0 + cloc;
            if (cg < K2) {
                const float bz0 = sbias[cloc], bz1 = sbias[cloc + 1];
                float2 v0, v1;
                v0.x = __expf(acc[i][nt][0] + bz0);
                v0.y = __expf(acc[i][nt][1] + bz1);
                v1.x = __expf(acc[i][nt][2] + bz0);
                v1.y = __expf(acc[i][nt][3] + bz1);
                *(float2*)(g_E + (size_t)r0 * K2P + cg) = v0;
                *(float2*)(g_E + (size_t)(r0 + 8) * K2P + cg) = v1;
            }
        }
    }
}

// ===========================================================================
// Kernel 2: per-position target energy (one warp per position, exact fp32)
// ===========================================================================
__global__ __launch_bounds__(256) void tg_kernel(
    const float* __restrict__ feats, const float* __restrict__ W,
    const float* __restrict__ bias, const void* __restrict__ target,
    const void* __restrict__ mask)
{
    const int warp = (blockIdx.x * blockDim.x + threadIdx.x) >> 5;
    const int lane = threadIdx.x & 31;
    if (warp >= M_TOT) return;

    long long t;
    if (g_t64) t = ((const long long*)target)[warp];
    else       t = (long long)((const int*)target)[warp];

    const float4* a  = (const float4*)(feats + (size_t)warp * HID);
    const float4* w4 = (const float4*)(W + (size_t)t * HID);
    float s = 0.0f;
#pragma unroll
    for (int u = 0; u < 4; u++) {
        float4 av = a[lane + u * 32];
        float4 wv = w4[lane + u * 32];
        s += av.x * wv.x + av.y * wv.y + av.z * wv.z + av.w * wv.w;
    }
#pragma unroll
    for (int off = 16; off; off >>= 1) s += __shfl_xor_sync(0xffffffffu, s, off);
    if (lane == 0)
        g_tg[warp] = mask_at(mask, warp) ? (s + bias[t]) : 0.0f;
}

// ===========================================================================
// Kernel 3: sequential forward scan, one block (64 thr) per batch element.
// Partition kept as normalized REAL vector pe[] + scalar logoff:
//   q_j = sum_i E[i][j] * pe[i];  pe <- q / q_0;  logoff += log(q_0)
// No per-element exp/log. Bulk-copy ring (4 stages, prefetch 3) as in R5.
// ===========================================================================
__global__ __launch_bounds__(64) void scan_kernel(
    const void* __restrict__ mask, float* __restrict__ out)
{
    __shared__ __align__(16) float Es[4][K2P];
    __shared__ __align__(8) unsigned long long mbar[4];
    __shared__ float pe[TAGS];
    __shared__ float s_q0;
    __shared__ float red[2];

    const int b = blockIdx.x;
    const int tid = threadIdx.x;
    const uint32_t mb = smem_u32(mbar);
    const uint32_t esb = smem_u32(Es);

    if (tid == 0) {
#pragma unroll
        for (int q = 0; q < 4; q++) MBAR_INIT(mb + 8 * q, 1);
    }
    // init: pe = E0_row / E0_row[0], logoff = log(E0_row[0])
    float e0 = 0.0f;
    if (tid < TAGS)
        e0 = g_E[(size_t)b * K2P + START_TAG * TAGS + tid];
    if (tid == 0) s_q0 = e0;
    __syncthreads();
    float logoff = 0.0f;
    if (tid == 0) logoff = __logf(s_q0);
    if (tid < TAGS) pe[tid] = e0 / s_q0;
    __syncthreads();

    // prefetch tiles for s = 1,2,3 into stages 0,1,2  (stage(s) = (s-1)&3)
    if (tid == 0) {
#pragma unroll
        for (int t = 1; t <= 3; t++) {
            int st = (t - 1) & 3;
            MBAR_EXPECT_TX(mb + 8 * st, K2P * 4);
            asm volatile(
                "cp.async.bulk.shared::cta.global.mbarrier::complete_tx::bytes [%0], [%1], %2, [%3];"
                :: "r"(esb + st * (K2P * 4)),
                   "l"(g_E + (size_t)(t * BATCH + b) * K2P),
                   "r"(K2P * 4), "r"(mb + 8 * st) : "memory");
        }
    }

    for (int s = 1; s < S_LEN; s++) {
        const int st = (s - 1) & 3;
        if (tid == 0 && s + 3 < S_LEN) {
            int ps = (s + 2) & 3;
            MBAR_EXPECT_TX(mb + 8 * ps, K2P * 4);
            asm volatile(
                "cp.async.bulk.shared::cta.global.mbarrier::complete_tx::bytes [%0], [%1], %2, [%3];"
                :: "r"(esb + ps * (K2P * 4)),
                   "l"(g_E + (size_t)((s + 3) * BATCH + b) * K2P),
                   "r"(K2P * 4), "r"(mb + 8 * ps) : "memory");
        }
        MBAR_WAIT(mb + 8 * st, ((s - 1) >> 2) & 1);

        float q = 0.0f;
        if (tid < TAGS) {
            const float* E = Es[st];
#pragma unroll
            for (int i = 0; i < TAGS; i++)
                q = fmaf(E[i * TAGS + tid], pe[i], q);
            if (tid == 0) s_q0 = q;
        }
        const bool m = mask_at(mask, s * BATCH + b);
        __syncthreads();            // pe reads done + s_q0 visible
        if (m) {
            if (tid < TAGS) pe[tid] = __fdividef(q, s_q0);
            if (tid == 0) logoff += __logf(s_q0);
        }
        __syncthreads();            // pe writes done before next step
    }

    // epilogue: loss contribution = log(pe[END]) + logoff - sum_s tg[s,b]
    float tg = 0.0f;
    for (int s = tid; s < S_LEN; s += 64) tg += g_tg[s * BATCH + b];
#pragma unroll
    for (int off = 16; off; off >>= 1) tg += __shfl_xor_sync(0xffffffffu, tg, off);
    if ((tid & 31) == 0) red[tid >> 5] = tg;
    __syncthreads();
    if (tid == 0) {
        float tgb = red[0] + red[1];
        float pEnd = __logf(pe[END_TAG]) + logoff;
        atomicAdd(out, (pEnd - tgb) / (float)BATCH);
    }
}

// ===========================================================================
extern "C" void kernel_launch(void* const* d_in, const int* in_sizes, int n_in,
                              void* d_out, int out_size)
{
    const float* feats  = (const float*)d_in[0];
    const float* W      = (const float*)d_in[1];
    const float* bias   = (const float*)d_in[2];
    const void*  target = d_in[3];
    const void*  mask   = (const void*)d_in[4];
    float* out = (float*)d_out;

    cudaFuncSetAttribute(gemm_tc_kernel,
                         cudaFuncAttributeMaxDynamicSharedMemorySize, GEMM_SMEM);

    init_kernel<<<1, 32>>>(out, target, mask);
    cvt_kernel<<<1184, 256>>>(feats, W);

    dim3 ggrid((K2 + BN - 1) / BN, M_TOT / BM);   // 20 x 256
    gemm_tc_kernel<<<ggrid, 256, GEMM_SMEM>>>(bias);

    tg_kernel<<<M_TOT / 8, 256>>>(feats, W, bias, target, mask);

    scan_kernel<<<BATCH, 64>>>(mask, out);
}

// round 8
// speedup vs baseline: 7.7155x; 1.1426x over previous
#include <cuda_runtime.h>
#include <cuda_bf16.h>
#include <math.h>
#include <stdint.h>

#define S_LEN 512
#define BATCH 64
#define HID 512
#define TAGS 50
#define K2 2500             // TAGS*TAGS
#define K2PH 2512           // padded row in halfs (5024 B, 16B mult)
#define START_TAG 48
#define END_TAG 49
#define M_TOT (S_LEN*BATCH) // 32768
#define NTILES 20           // ceil(2500/128)
#define NPAD (NTILES*128)   // 2560

// Scratch (no allocations allowed)
__device__ __align__(1024) unsigned short g_Eh[(size_t)M_TOT * K2PH];      // bf16 E, ~165 MB
__device__ __align__(1024) unsigned int g_Ah[(size_t)M_TOT * HID / 2];     // bf16 feats, tiled
__device__ __align__(1024) unsigned int g_Wh[(size_t)NPAD * HID / 2];      // bf16 W, tiled+padded
__device__ float g_tg[M_TOT];
__device__ int g_t64;   // target stored as int64 (vs int32)
__device__ int g_m32;   // mask stored as int32 (vs bool/byte)

// ===========================================================================
// PTX helpers
// ===========================================================================
__device__ __forceinline__ uint32_t smem_u32(const void* p) {
    uint32_t a;
    asm("{ .reg .u64 t; cvta.to.shared.u64 t, %1; cvt.u32.u64 %0, t; }" : "=r"(a) : "l"(p));
    return a;
}
#define MBAR_INIT(addr, cnt) \
    asm volatile("mbarrier.init.shared.b64 [%0], %1;" :: "r"(addr), "r"(cnt) : "memory")
#define MBAR_EXPECT_TX(addr, bytes) \
    asm volatile("mbarrier.arrive.expect_tx.shared.b64 _, [%0], %1;" :: "r"(addr), "r"(bytes) : "memory")
#define MBAR_WAIT(addr, par) do {                                              \
    uint32_t _m = (addr), _p = (par), _d;                                      \
    asm volatile("{\n\t.reg .pred p;\n\t"                                      \
        "mbarrier.try_wait.parity.acquire.cta.shared::cta.b64 p, [%1], %2;\n\t"\
        "selp.b32 %0, 1, 0, p;\n\t}" : "=r"(_d) : "r"(_m), "r"(_p) : "memory");\
    if (!_d) {                                                                 \
        asm volatile("{\n\t.reg .pred P1;\n\t"                                 \
            "W%=:\n\t"                                                         \
            "mbarrier.try_wait.parity.acquire.cta.shared::cta.b64 P1, [%0], %1, 0x989680;\n\t" \
            "@P1 bra.uni D%=;\n\t"                                             \
            "bra.uni W%=;\n\t"                                                 \
            "D%=:\n\t}" :: "r"(_m), "r"(_p) : "memory");                       \
    }                                                                          \
} while (0)
#define BULK_G2S(dst, src, bytes, bar) \
    asm volatile("cp.async.bulk.shared::cta.global.mbarrier::complete_tx::bytes [%0], [%1], %2, [%3];" \
        :: "r"(dst), "l"(src), "r"(bytes), "r"(bar) : "memory")

__device__ __forceinline__ uint32_t pack_bf16x2(float lo, float hi) {
    uint32_t r;
    asm("cvt.rn.bf16x2.f32 %0, %1, %2;" : "=r"(r) : "f"(hi), "f"(lo));
    return r;
}
__device__ __forceinline__ float bf2f(unsigned short u) {
    return __uint_as_float(((unsigned int)u) << 16);
}
__device__ __forceinline__ void mma_bf16(float& d0, float& d1, float& d2, float& d3,
                                         uint32_t a0, uint32_t a1, uint32_t a2, uint32_t a3,
                                         uint32_t b0, uint32_t b1) {
    asm volatile(
        "mma.sync.aligned.m16n8k16.row.col.f32.bf16.bf16.f32 "
        "{%0,%1,%2,%3},{%4,%5,%6,%7},{%8,%9},{%0,%1,%2,%3};"
        : "+f"(d0), "+f"(d1), "+f"(d2), "+f"(d3)
        : "r"(a0), "r"(a1), "r"(a2), "r"(a3), "r"(b0), "r"(b1));
}

// ===========================================================================
// Kernel 0: zero output + detect input storage widths
// ===========================================================================
__global__ void init_kernel(float* out, const void* target, const void* mask) {
    if (threadIdx.x == 0) {
        out[0] = 0.0f;
        const unsigned int* tw = (const unsigned int*)target;
        unsigned int nz = 0;
#pragma unroll
        for (int q = 0; q < 64; q++) nz |= tw[2 * q + 1];
        g_t64 = (nz == 0) ? 1 : 0;
        const unsigned int* mw = (const unsigned int*)mask;
        unsigned int big = 0;
#pragma unroll
        for (int q = 0; q < 64; q++) big |= (mw[q] > 1u) ? 1u : 0u;
        g_m32 = big ? 0 : 1;
    }
}
__device__ __forceinline__ bool mask_at(const void* mask, int idx) {
    if (g_m32) return ((const int*)mask)[idx] != 0;
    return ((const unsigned char*)mask)[idx] != 0;
}

// ===========================================================================
// Kernel 0b: convert feats/W to bf16 AND tile:
// tile = 128 rows x 32 k-halfs = 8 KB contiguous  (layout [rowtile][chunk][row][32h])
// ===========================================================================
__global__ __launch_bounds__(256) void cvt_kernel(
    const float* __restrict__ A, const float* __restrict__ W)
{
    const int stride = gridDim.x * blockDim.x;
    // A: 32768 rows x 256 float2
    for (int id = blockIdx.x * blockDim.x + threadIdx.x; id < M_TOT * 256; id += stride) {
        int m = id >> 8, kp = id & 255;
        float2 v = ((const float2*)A)[id];
        int tile = (m >> 7) * 16 + (kp >> 4);
        g_Ah[tile * 2048 + (m & 127) * 16 + (kp & 15)] = pack_bf16x2(v.x, v.y);
    }
    // W: 2560 rows (>=2500 zero-padded) x 256 float2
    for (int id = blockIdx.x * blockDim.x + threadIdx.x; id < NPAD * 256; id += stride) {
        int n = id >> 8, kp = id & 255;
        unsigned int o = 0;
        if (n < K2) {
            float2 v = ((const float2*)W)[id];
            o = pack_bf16x2(v.x, v.y);
        }
        int tile = (n >> 7) * 16 + (kp >> 4);
        g_Wh[tile * 2048 + (n & 127) * 16 + (kp & 15)] = o;
    }
}

// ===========================================================================
// Kernel 1: bf16 mma.sync GEMM + exp epilogue -> g_Eh (bf16)
// BM=BN=128, chunks of k=32. 256 threads, warp grid 2(m)x4(n), warp tile 64x32.
// Fills: 2 cp.async.bulk per chunk (8KB A + 8KB B), double-buffered w/ mbarrier.
// Fragments: one LDS.128 per row covers BOTH k16 MMA steps (k-permuted
// identically on A and B: slot{2t,2t+1}->phys{8t,8t+1}, slot{2t+8,2t+9}->phys{8t+2,8t+3}).
// ===========================================================================
#define NCHUNK 16
#define TILEB 8192
#define BUFSZ (2*TILEB)                 // A+B per buffer
#define GEMM_SMEM (2*BUFSZ + 1024)      // + bias(512) + mbars

__global__ __launch_bounds__(256, 2) void gemm_tc_kernel(const float* __restrict__ bias)
{
    extern __shared__ char smem[];
    const uint32_t sbase = smem_u32(smem);
    const int tid = threadIdx.x;
    const int nt0 = blockIdx.x;        // n tile
    const int mt0 = blockIdx.y;        // m tile
    const int n0 = nt0 * 128;
    const int m0 = mt0 * 128;
    float* sbias = (float*)(smem + 2 * BUFSZ);
    const uint32_t mb = sbase + 2 * BUFSZ + 512;

    if (tid < 128) {
        int n = n0 + tid;
        sbias[tid] = (n < K2) ? bias[n] : 0.0f;
    }
    if (tid == 0) { MBAR_INIT(mb, 1); MBAR_INIT(mb + 8, 1); }
    __syncthreads();

    const char* gA = (const char*)g_Ah + (size_t)mt0 * 16 * TILEB;
    const char* gW = (const char*)g_Wh + (size_t)nt0 * 16 * TILEB;

    auto issue = [&](int c) {
        const int buf = c & 1;
        const uint32_t bar = mb + 8 * buf;
        MBAR_EXPECT_TX(bar, 2 * TILEB);
        BULK_G2S(sbase + buf * BUFSZ,         gA + (size_t)c * TILEB, TILEB, bar);
        BULK_G2S(sbase + buf * BUFSZ + TILEB, gW + (size_t)c * TILEB, TILEB, bar);
    };
    if (tid == 0) issue(0);

    const int w = tid >> 5;
    const int lane = tid & 31;
    const int g = lane >> 2;       // row within 8
    const int t = lane & 3;        // 16B segment
    const int wm = w >> 2;         // 0..1 -> m offset wm*64
    const int wn = w & 3;          // 0..3 -> n offset wn*32

    float acc[4][4][4];
#pragma unroll
    for (int i = 0; i < 4; i++)
#pragma unroll
        for (int j = 0; j < 4; j++)
#pragma unroll
            for (int q = 0; q < 4; q++) acc[i][j][q] = 0.0f;

    for (int c = 0; c < NCHUNK; c++) {
        if (tid == 0 && c + 1 < NCHUNK) issue(c + 1);
        MBAR_WAIT(mb + 8 * (c & 1), (c >> 1) & 1);

        const char* sA = smem + (c & 1) * BUFSZ;
        const char* sB = sA + TILEB;

        uint4 bfr[4];
#pragma unroll
        for (int nt = 0; nt < 4; nt++)
            bfr[nt] = *(const uint4*)(sB + (wn * 32 + nt * 8 + g) * 64 + t * 16);
#pragma unroll
        for (int i = 0; i < 4; i++) {
            const int ra = wm * 64 + i * 16 + g;
            uint4 a0 = *(const uint4*)(sA + ra * 64 + t * 16);
            uint4 a1 = *(const uint4*)(sA + (ra + 8) * 64 + t * 16);
#pragma unroll
            for (int nt = 0; nt < 4; nt++) {
                mma_bf16(acc[i][nt][0], acc[i][nt][1], acc[i][nt][2], acc[i][nt][3],
                         a0.x, a1.x, a0.y, a1.y, bfr[nt].x, bfr[nt].y);
                mma_bf16(acc[i][nt][0], acc[i][nt][1], acc[i][nt][2], acc[i][nt][3],
                         a0.z, a1.z, a0.w, a1.w, bfr[nt].z, bfr[nt].w);
            }
        }
        __syncthreads();   // all warps done with this buffer before refill
    }

    // epilogue: E = bf16(exp(D + bias)); d0,d1 -> (row g, cols 2t,2t+1), d2,d3 -> row g+8
    unsigned int* Eu = (unsigned int*)g_Eh;
#pragma unroll
    for (int i = 0; i < 4; i++) {
        const int r0 = m0 + wm * 64 + i * 16 + g;
#pragma unroll
        for (int nt = 0; nt < 4; nt++) {
            const int cloc = wn * 32 + nt * 8 + 2 * t;
            const int cg = n0 + cloc;
            if (cg < K2) {
                const float bz0 = sbias[cloc], bz1 = sbias[cloc + 1];
                unsigned int u0 = pack_bf16x2(__expf(acc[i][nt][0] + bz0),
                                              __expf(acc[i][nt][1] + bz1));
                unsigned int u1 = pack_bf16x2(__expf(acc[i][nt][2] + bz0),
                                              __expf(acc[i][nt][3] + bz1));
                Eu[((size_t)r0 * K2PH + cg) >> 1] = u0;
                Eu[((size_t)(r0 + 8) * K2PH + cg) >> 1] = u1;
            }
        }
    }
}

// ===========================================================================
// Kernel 2: per-position target energy (one warp per position, exact fp32)
// ===========================================================================
__global__ __launch_bounds__(256) void tg_kernel(
    const float* __restrict__ feats, const float* __restrict__ W,
    const float* __restrict__ bias, const void* __restrict__ target,
    const void* __restrict__ mask)
{
    const int warp = (blockIdx.x * blockDim.x + threadIdx.x) >> 5;
    const int lane = threadIdx.x & 31;
    if (warp >= M_TOT) return;

    long long t;
    if (g_t64) t = ((const long long*)target)[warp];
    else       t = (long long)((const int*)target)[warp];

    const float4* a  = (const float4*)(feats + (size_t)warp * HID);
    const float4* w4 = (const float4*)(W + (size_t)t * HID);
    float s = 0.0f;
#pragma unroll
    for (int u = 0; u < 4; u++) {
        float4 av = a[lane + u * 32];
        float4 wv = w4[lane + u * 32];
        s += av.x * wv.x + av.y * wv.y + av.z * wv.z + av.w * wv.w;
    }
#pragma unroll
    for (int off = 16; off; off >>= 1) s += __shfl_xor_sync(0xffffffffu, s, off);
    if (lane == 0)
        g_tg[warp] = mask_at(mask, warp) ? (s + bias[t]) : 0.0f;
}

// ===========================================================================
// Kernel 3: sequential forward scan, one block (64 thr) per batch element.
// Normalized real-domain partition: q_j = sum_i E[i][j]*pe[i]; pe<-q/q0;
// logoff += log(q0). E is bf16; 4-deep bulk-copy ring, prefetch distance 3.
// ===========================================================================
#define STAGEB (K2PH * 2)    // 5024 bytes per stage

__global__ __launch_bounds__(64) void scan_kernel(
    const void* __restrict__ mask, float* __restrict__ out)
{
    __shared__ __align__(16) unsigned short Es[4][K2PH];
    __shared__ __align__(8) unsigned long long mbar[4];
    __shared__ float pe[TAGS];
    __shared__ float s_q0;
    __shared__ float red[2];

    const int b = blockIdx.x;
    const int tid = threadIdx.x;
    const uint32_t mb = smem_u32(mbar);
    const uint32_t esb = smem_u32(Es);

    if (tid == 0) {
#pragma unroll
        for (int q = 0; q < 4; q++) MBAR_INIT(mb + 8 * q, 1);
    }
    // init: pe = E0_row / E0_row[0], logoff = log(E0_row[0])
    float e0 = 0.0f;
    if (tid < TAGS)
        e0 = bf2f(g_Eh[(size_t)b * K2PH + START_TAG * TAGS + tid]);
    if (tid == 0) s_q0 = e0;
    __syncthreads();
    float logoff = 0.0f;
    if (tid == 0) logoff = __logf(s_q0);
    if (tid < TAGS) pe[tid] = e0 / s_q0;
    __syncthreads();

    if (tid == 0) {
#pragma unroll
        for (int t = 1; t <= 3; t++) {
            int st = (t - 1) & 3;
            MBAR_EXPECT_TX(mb + 8 * st, STAGEB);
            BULK_G2S(esb + st * STAGEB,
                     (const char*)g_Eh + (size_t)(t * BATCH + b) * STAGEB,
                     STAGEB, mb + 8 * st);
        }
    }

    for (int s = 1; s < S_LEN; s++) {
        const int st = (s - 1) & 3;
        if (tid == 0 && s + 3 < S_LEN) {
            int ps = (s + 2) & 3;
            MBAR_EXPECT_TX(mb + 8 * ps, STAGEB);
            BULK_G2S(esb + ps * STAGEB,
                     (const char*)g_Eh + (size_t)((s + 3) * BATCH + b) * STAGEB,
                     STAGEB, mb + 8 * ps);
        }
        MBAR_WAIT(mb + 8 * st, ((s - 1) >> 2) & 1);

        float q = 0.0f;
        if (tid < TAGS) {
            const unsigned short* E = Es[st];
            float a0 = 0.0f, a1 = 0.0f, a2 = 0.0f, a3 = 0.0f;
#pragma unroll
            for (int i = 0; i < 48; i += 4) {
                a0 = fmaf(bf2f(E[(i + 0) * TAGS + tid]), pe[i + 0], a0);
                a1 = fmaf(bf2f(E[(i + 1) * TAGS + tid]), pe[i + 1], a1);
                a2 = fmaf(bf2f(E[(i + 2) * TAGS + tid]), pe[i + 2], a2);
                a3 = fmaf(bf2f(E[(i + 3) * TAGS + tid]), pe[i + 3], a3);
            }
            a0 = fmaf(bf2f(E[48 * TAGS + tid]), pe[48], a0);
            a1 = fmaf(bf2f(E[49 * TAGS + tid]), pe[49], a1);
            q = (a0 + a1) + (a2 + a3);
            if (tid == 0) s_q0 = q;
        }
        const bool m = mask_at(mask, s * BATCH + b);
        __syncthreads();            // pe reads done + s_q0 visible
        if (m) {
            if (tid < TAGS) pe[tid] = __fdividef(q, s_q0);
            if (tid == 0) logoff += __logf(s_q0);
        }
        __syncthreads();            // pe writes done before next step
    }

    // epilogue: loss contribution = log(pe[END]) + logoff - sum_s tg[s,b]
    float tg = 0.0f;
    for (int s = tid; s < S_LEN; s += 64) tg += g_tg[s * BATCH + b];
#pragma unroll
    for (int off = 16; off; off >>= 1) tg += __shfl_xor_sync(0xffffffffu, tg, off);
    if ((tid & 31) == 0) red[tid >> 5] = tg;
    __syncthreads();
    if (tid == 0) {
        float tgb = red[0] + red[1];
        float pEnd = __logf(pe[END_TAG]) + logoff;
        atomicAdd(out, (pEnd - tgb) / (float)BATCH);
    }
}

// ===========================================================================
extern "C" void kernel_launch(void* const* d_in, const int* in_sizes, int n_in,
                              void* d_out, int out_size)
{
    const float* feats  = (const float*)d_in[0];
    const float* W      = (const float*)d_in[1];
    const float* bias   = (const float*)d_in[2];
    const void*  target = d_in[3];
    const void*  mask   = (const void*)d_in[4];
    float* out = (float*)d_out;

    cudaFuncSetAttribute(gemm_tc_kernel,
                         cudaFuncAttributeMaxDynamicSharedMemorySize, GEMM_SMEM);

    init_kernel<<<1, 32>>>(out, target, mask);
    cvt_kernel<<<1184, 256>>>(feats, W);

    dim3 ggrid(NTILES, M_TOT / 128);   // 20 x 256
    gemm_tc_kernel<<<ggrid, 256, GEMM_SMEM>>>(bias);

    tg_kernel<<<M_TOT / 8, 256>>>(feats, W, bias, target, mask);

    scan_kernel<<<BATCH, 64>>>(mask, out);
}

// round 9
// speedup vs baseline: 7.8417x; 1.0164x over previous
#include <cuda_runtime.h>
#include <cuda_bf16.h>
#include <math.h>
#include <stdint.h>

#define S_LEN 512
#define BATCH 64
#define HID 512
#define TAGS 50
#define K2 2500             // TAGS*TAGS
#define K2PH 2512           // padded row in halfs (5024 B, 16B mult)
#define START_TAG 48
#define END_TAG 49
#define M_TOT (S_LEN*BATCH) // 32768
#define NTILES 20           // ceil(2500/128)
#define NPAD (NTILES*128)   // 2560

// Scratch (no allocations allowed)
__device__ __align__(1024) unsigned short g_Eh[(size_t)M_TOT * K2PH];      // bf16 E, ~165 MB
__device__ __align__(1024) unsigned int g_Ah[(size_t)M_TOT * HID / 2];     // bf16 feats, tiled
__device__ __align__(1024) unsigned int g_Wh[(size_t)NPAD * HID / 2];      // bf16 W, tiled+padded
__device__ float g_tg[M_TOT];
__device__ int g_t64;   // target stored as int64 (vs int32)
__device__ int g_m32;   // mask stored as int32 (vs bool/byte)

// ===========================================================================
// PTX helpers
// ===========================================================================
__device__ __forceinline__ uint32_t smem_u32(const void* p) {
    uint32_t a;
    asm("{ .reg .u64 t; cvta.to.shared.u64 t, %1; cvt.u32.u64 %0, t; }" : "=r"(a) : "l"(p));
    return a;
}
#define MBAR_INIT(addr, cnt) \
    asm volatile("mbarrier.init.shared.b64 [%0], %1;" :: "r"(addr), "r"(cnt) : "memory")
#define MBAR_EXPECT_TX(addr, bytes) \
    asm volatile("mbarrier.arrive.expect_tx.shared.b64 _, [%0], %1;" :: "r"(addr), "r"(bytes) : "memory")
#define MBAR_WAIT(addr, par) do {                                              \
    uint32_t _m = (addr), _p = (par), _d;                                      \
    asm volatile("{\n\t.reg .pred p;\n\t"                                      \
        "mbarrier.try_wait.parity.acquire.cta.shared::cta.b64 p, [%1], %2;\n\t"\
        "selp.b32 %0, 1, 0, p;\n\t}" : "=r"(_d) : "r"(_m), "r"(_p) : "memory");\
    if (!_d) {                                                                 \
        asm volatile("{\n\t.reg .pred P1;\n\t"                                 \
            "W%=:\n\t"                                                         \
            "mbarrier.try_wait.parity.acquire.cta.shared::cta.b64 P1, [%0], %1, 0x989680;\n\t" \
            "@P1 bra.uni D%=;\n\t"                                             \
            "bra.uni W%=;\n\t"                                                 \
            "D%=:\n\t}" :: "r"(_m), "r"(_p) : "memory");                       \
    }                                                                          \
} while (0)
#define BULK_G2S(dst, src, bytes, bar) \
    asm volatile("cp.async.bulk.shared::cta.global.mbarrier::complete_tx::bytes [%0], [%1], %2, [%3];" \
        :: "r"(dst), "l"(src), "r"(bytes), "r"(bar) : "memory")

__device__ __forceinline__ uint32_t pack_bf16x2(float lo, float hi) {
    uint32_t r;
    asm("cvt.rn.bf16x2.f32 %0, %1, %2;" : "=r"(r) : "f"(hi), "f"(lo));
    return r;
}
__device__ __forceinline__ float bf2f(unsigned short u) {
    return __uint_as_float(((unsigned int)u) << 16);
}
// FFMA-only exp: z = x*log2e; n = rne(z) via magic-number; 2^f deg-4 Taylor;
// exponent injected via integer add on float bits. Rel err <= 4.2e-5.
__device__ __forceinline__ float fast_exp(float x) {
    float z = __fmul_rn(x, 1.44269504f);
    float t = __fadd_rn(z, 12582912.0f);      // 2^23 + 2^22 magic
    float n = __fadd_rn(t, -12582912.0f);
    float f = __fadd_rn(z, -n);
    float p = 0.00961812910f;
    p = fmaf(p, f, 0.05550410866f);
    p = fmaf(p, f, 0.24022650696f);
    p = fmaf(p, f, 0.69314718056f);
    p = fmaf(p, f, 1.0f);
    return __int_as_float(__float_as_int(p) + (__float_as_int(t) << 23));
}
__device__ __forceinline__ void mma_bf16(float& d0, float& d1, float& d2, float& d3,
                                         uint32_t a0, uint32_t a1, uint32_t a2, uint32_t a3,
                                         uint32_t b0, uint32_t b1) {
    asm volatile(
        "mma.sync.aligned.m16n8k16.row.col.f32.bf16.bf16.f32 "
        "{%0,%1,%2,%3},{%4,%5,%6,%7},{%8,%9},{%0,%1,%2,%3};"
        : "+f"(d0), "+f"(d1), "+f"(d2), "+f"(d3)
        : "r"(a0), "r"(a1), "r"(a2), "r"(a3), "r"(b0), "r"(b1));
}

// ===========================================================================
// Kernel 0: zero output + detect input storage widths
// ===========================================================================
__global__ void init_kernel(float* out, const void* target, const void* mask) {
    if (threadIdx.x == 0) {
        out[0] = 0.0f;
        const unsigned int* tw = (const unsigned int*)target;
        unsigned int nz = 0;
#pragma unroll
        for (int q = 0; q < 64; q++) nz |= tw[2 * q + 1];
        g_t64 = (nz == 0) ? 1 : 0;
        const unsigned int* mw = (const unsigned int*)mask;
        unsigned int big = 0;
#pragma unroll
        for (int q = 0; q < 64; q++) big |= (mw[q] > 1u) ? 1u : 0u;
        g_m32 = big ? 0 : 1;
    }
}
__device__ __forceinline__ bool mask_at(const void* mask, int idx) {
    if (g_m32) return ((const int*)mask)[idx] != 0;
    return ((const unsigned char*)mask)[idx] != 0;
}

// ===========================================================================
// Kernel 0b: convert feats/W to bf16 AND tile:
// tile = 128 rows x 32 k-halfs = 8 KB contiguous  (layout [rowtile][chunk][row][32h])
// ===========================================================================
__global__ __launch_bounds__(256) void cvt_kernel(
    const float* __restrict__ A, const float* __restrict__ W)
{
    const int stride = gridDim.x * blockDim.x;
    for (int id = blockIdx.x * blockDim.x + threadIdx.x; id < M_TOT * 256; id += stride) {
        int m = id >> 8, kp = id & 255;
        float2 v = ((const float2*)A)[id];
        int tile = (m >> 7) * 16 + (kp >> 4);
        g_Ah[tile * 2048 + (m & 127) * 16 + (kp & 15)] = pack_bf16x2(v.x, v.y);
    }
    for (int id = blockIdx.x * blockDim.x + threadIdx.x; id < NPAD * 256; id += stride) {
        int n = id >> 8, kp = id & 255;
        unsigned int o = 0;
        if (n < K2) {
            float2 v = ((const float2*)W)[id];
            o = pack_bf16x2(v.x, v.y);
        }
        int tile = (n >> 7) * 16 + (kp >> 4);
        g_Wh[tile * 2048 + (n & 127) * 16 + (kp & 15)] = o;
    }
}

// ===========================================================================
// Kernel 1: bf16 mma.sync GEMM + fast-exp epilogue -> g_Eh (bf16)
// BM=BN=128, k chunks of 32. 256 threads, warp grid 2(m)x4(n), warp tile 64x32.
// Fills: 2 cp.async.bulk per chunk, double-buffered w/ mbarrier.
// Epilogue: exp via FFMA poly, staged through padded SMEM tile, coalesced
// 16B-segment stores (2 full 256B rows per warp instruction).
// ===========================================================================
#define NCHUNK 16
#define TILEB 8192
#define BUFSZ (2*TILEB)                 // A+B per buffer
#define RPH 136                         // staging row stride in halfs (272 B)
#define STAGEBYTES (128 * RPH * 2)      // 34816
#define GEMM_SMEM (STAGEBYTES + 1024)   // staging overlays the two data buffers

__global__ __launch_bounds__(256, 2) void gemm_tc_kernel(const float* __restrict__ bias)
{
    extern __shared__ char smem[];
    const uint32_t sbase = smem_u32(smem);
    const int tid = threadIdx.x;
    const int nt0 = blockIdx.x;        // n tile
    const int mt0 = blockIdx.y;        // m tile
    const int n0 = nt0 * 128;
    const int m0 = mt0 * 128;
    float* sbias = (float*)(smem + STAGEBYTES);
    const uint32_t mb = sbase + STAGEBYTES + 512;

    if (tid < 128) {
        int n = n0 + tid;
        sbias[tid] = (n < K2) ? bias[n] : 0.0f;
    }
    if (tid == 0) { MBAR_INIT(mb, 1); MBAR_INIT(mb + 8, 1); }
    __syncthreads();

    const char* gA = (const char*)g_Ah + (size_t)mt0 * 16 * TILEB;
    const char* gW = (const char*)g_Wh + (size_t)nt0 * 16 * TILEB;

    auto issue = [&](int c) {
        const int buf = c & 1;
        const uint32_t bar = mb + 8 * buf;
        MBAR_EXPECT_TX(bar, 2 * TILEB);
        BULK_G2S(sbase + buf * BUFSZ,         gA + (size_t)c * TILEB, TILEB, bar);
        BULK_G2S(sbase + buf * BUFSZ + TILEB, gW + (size_t)c * TILEB, TILEB, bar);
    };
    if (tid == 0) issue(0);

    const int w = tid >> 5;
    const int lane = tid & 31;
    const int g = lane >> 2;       // row within 8
    const int t = lane & 3;        // 16B segment
    const int wm = w >> 2;         // 0..1 -> m offset wm*64
    const int wn = w & 3;          // 0..3 -> n offset wn*32

    float acc[4][4][4];
#pragma unroll
    for (int i = 0; i < 4; i++)
#pragma unroll
        for (int j = 0; j < 4; j++)
#pragma unroll
            for (int q = 0; q < 4; q++) acc[i][j][q] = 0.0f;

    for (int c = 0; c < NCHUNK; c++) {
        if (tid == 0 && c + 1 < NCHUNK) issue(c + 1);
        MBAR_WAIT(mb + 8 * (c & 1), (c >> 1) & 1);

        const char* sA = smem + (c & 1) * BUFSZ;
        const char* sB = sA + TILEB;

        uint4 bfr[4];
#pragma unroll
        for (int nt = 0; nt < 4; nt++)
            bfr[nt] = *(const uint4*)(sB + (wn * 32 + nt * 8 + g) * 64 + t * 16);
#pragma unroll
        for (int i = 0; i < 4; i++) {
            const int ra = wm * 64 + i * 16 + g;
            uint4 a0 = *(const uint4*)(sA + ra * 64 + t * 16);
            uint4 a1 = *(const uint4*)(sA + (ra + 8) * 64 + t * 16);
#pragma unroll
            for (int nt = 0; nt < 4; nt++) {
                mma_bf16(acc[i][nt][0], acc[i][nt][1], acc[i][nt][2], acc[i][nt][3],
                         a0.x, a1.x, a0.y, a1.y, bfr[nt].x, bfr[nt].y);
                mma_bf16(acc[i][nt][0], acc[i][nt][1], acc[i][nt][2], acc[i][nt][3],
                         a0.z, a1.z, a0.w, a1.w, bfr[nt].z, bfr[nt].w);
            }
        }
        __syncthreads();   // all warps done with this buffer before refill
    }

    // ---- epilogue: E = bf16(fast_exp(D + bias)) into padded SMEM stage ----
    unsigned short* stg = (unsigned short*)smem;
#pragma unroll
    for (int i = 0; i < 4; i++) {
        const int rloc = wm * 64 + i * 16 + g;
#pragma unroll
        for (int nt = 0; nt < 4; nt++) {
            const int cloc = wn * 32 + nt * 8 + 2 * t;
            const float bz0 = sbias[cloc], bz1 = sbias[cloc + 1];
            unsigned int u0 = pack_bf16x2(fast_exp(acc[i][nt][0] + bz0),
                                          fast_exp(acc[i][nt][1] + bz1));
            unsigned int u1 = pack_bf16x2(fast_exp(acc[i][nt][2] + bz0),
                                          fast_exp(acc[i][nt][3] + bz1));
            *(unsigned int*)&stg[rloc * RPH + cloc] = u0;
            *(unsigned int*)&stg[(rloc + 8) * RPH + cloc] = u1;
        }
    }
    __syncthreads();

    // ---- coalesced store-out: 2048 16B segments, 2 full rows per warp instr ----
#pragma unroll
    for (int it = 0; it < 8; it++) {
        int u = tid + it * 256;
        int r = u >> 4;            // 0..127
        int sg = u & 15;           // 16B segment within row
        int colh = sg * 8;         // half index within row
        if (n0 + colh + 8 <= K2PH) {
            uint4 v = *(const uint4*)&stg[r * RPH + colh];
            *(uint4*)&g_Eh[(size_t)(m0 + r) * K2PH + n0 + colh] = v;
        }
    }
}

// ===========================================================================
// Kernel 2: per-position target energy (one warp per position, exact fp32)
// ===========================================================================
__global__ __launch_bounds__(256) void tg_kernel(
    const float* __restrict__ feats, const float* __restrict__ W,
    const float* __restrict__ bias, const void* __restrict__ target,
    const void* __restrict__ mask)
{
    const int warp = (blockIdx.x * blockDim.x + threadIdx.x) >> 5;
    const int lane = threadIdx.x & 31;
    if (warp >= M_TOT) return;

    long long t;
    if (g_t64) t = ((const long long*)target)[warp];
    else       t = (long long)((const int*)target)[warp];

    const float4* a  = (const float4*)(feats + (size_t)warp * HID);
    const float4* w4 = (const float4*)(W + (size_t)t * HID);
    float s = 0.0f;
#pragma unroll
    for (int u = 0; u < 4; u++) {
        float4 av = a[lane + u * 32];
        float4 wv = w4[lane + u * 32];
        s += av.x * wv.x + av.y * wv.y + av.z * wv.z + av.w * wv.w;
    }
#pragma unroll
    for (int off = 16; off; off >>= 1) s += __shfl_xor_sync(0xffffffffu, s, off);
    if (lane == 0)
        g_tg[warp] = mask_at(mask, warp) ? (s + bias[t]) : 0.0f;
}

// ===========================================================================
// Kernel 3: sequential forward scan, one block (64 thr) per batch element.
// Normalized real-domain partition: q_j = sum_i E[i][j]*pe[i]; pe<-q/q0;
// logoff += log(q0). E is bf16; 8-deep bulk-copy ring, prefetch distance 7.
// ===========================================================================
#define NSTG 8
#define STAGEB (K2PH * 2)    // 5024 bytes per stage

__global__ __launch_bounds__(64) void scan_kernel(
    const void* __restrict__ mask, float* __restrict__ out)
{
    __shared__ __align__(16) unsigned short Es[NSTG][K2PH];
    __shared__ __align__(8) unsigned long long mbar[NSTG];
    __shared__ float pe[TAGS];
    __shared__ float s_q0;
    __shared__ float red[2];

    const int b = blockIdx.x;
    const int tid = threadIdx.x;
    const uint32_t mb = smem_u32(mbar);
    const uint32_t esb = smem_u32(Es);

    if (tid == 0) {
#pragma unroll
        for (int q = 0; q < NSTG; q++) MBAR_INIT(mb + 8 * q, 1);
    }
    // init: pe = E0_row / E0_row[0], logoff = log(E0_row[0])
    float e0 = 0.0f;
    if (tid < TAGS)
        e0 = bf2f(g_Eh[(size_t)b * K2PH + START_TAG * TAGS + tid]);
    if (tid == 0) s_q0 = e0;
    __syncthreads();
    float logoff = 0.0f;
    if (tid == 0) logoff = __logf(s_q0);
    if (tid < TAGS) pe[tid] = e0 / s_q0;
    __syncthreads();

    if (tid == 0) {
#pragma unroll
        for (int t = 1; t <= NSTG - 1; t++) {
            int st = (t - 1) & (NSTG - 1);
            MBAR_EXPECT_TX(mb + 8 * st, STAGEB);
            BULK_G2S(esb + st * STAGEB,
                     (const char*)g_Eh + (size_t)(t * BATCH + b) * STAGEB,
                     STAGEB, mb + 8 * st);
        }
    }

    for (int s = 1; s < S_LEN; s++) {
        const int st = (s - 1) & (NSTG - 1);
        if (tid == 0 && s + NSTG - 1 < S_LEN) {
            int ps = (s + NSTG - 2) & (NSTG - 1);
            MBAR_EXPECT_TX(mb + 8 * ps, STAGEB);
            BULK_G2S(esb + ps * STAGEB,
                     (const char*)g_Eh + (size_t)((s + NSTG - 1) * BATCH + b) * STAGEB,
                     STAGEB, mb + 8 * ps);
        }
        MBAR_WAIT(mb + 8 * st, ((s - 1) >> 3) & 1);

        float q = 0.0f;
        if (tid < TAGS) {
            const unsigned short* E = Es[st];
            float a0 = 0.0f, a1 = 0.0f, a2 = 0.0f, a3 = 0.0f;
#pragma unroll
            for (int i = 0; i < 48; i += 4) {
                a0 = fmaf(bf2f(E[(i + 0) * TAGS + tid]), pe[i + 0], a0);
                a1 = fmaf(bf2f(E[(i + 1) * TAGS + tid]), pe[i + 1], a1);
                a2 = fmaf(bf2f(E[(i + 2) * TAGS + tid]), pe[i + 2], a2);
                a3 = fmaf(bf2f(E[(i + 3) * TAGS + tid]), pe[i + 3], a3);
            }
            a0 = fmaf(bf2f(E[48 * TAGS + tid]), pe[48], a0);
            a1 = fmaf(bf2f(E[49 * TAGS + tid]), pe[49], a1);
            q = (a0 + a1) + (a2 + a3);
            if (tid == 0) s_q0 = q;
        }
        const bool m = mask_at(mask, s * BATCH + b);
        __syncthreads();            // pe reads done + s_q0 visible
        if (m) {
            if (tid < TAGS) pe[tid] = __fdividef(q, s_q0);
            if (tid == 0) logoff += __logf(s_q0);
        }
        __syncthreads();            // pe writes done before next step
    }

    // epilogue: loss contribution = log(pe[END]) + logoff - sum_s tg[s,b]
    float tg = 0.0f;
    for (int s = tid; s < S_LEN; s += 64) tg += g_tg[s * BATCH + b];
#pragma unroll
    for (int off = 16; off; off >>= 1) tg += __shfl_xor_sync(0xffffffffu, tg, off);
    if ((tid & 31) == 0) red[tid >> 5] = tg;
    __syncthreads();
    if (tid == 0) {
        float tgb = red[0] + red[1];
        float pEnd = __logf(pe[END_TAG]) + logoff;
        atomicAdd(out, (pEnd - tgb) / (float)BATCH);
    }
}

// ===========================================================================
extern "C" void kernel_launch(void* const* d_in, const int* in_sizes, int n_in,
                              void* d_out, int out_size)
{
    const float* feats  = (const float*)d_in[0];
    const float* W      = (const float*)d_in[1];
    const float* bias   = (const float*)d_in[2];
    const void*  target = d_in[3];
    const void*  mask   = (const void*)d_in[4];
    float* out = (float*)d_out;

    cudaFuncSetAttribute(gemm_tc_kernel,
                         cudaFuncAttributeMaxDynamicSharedMemorySize, GEMM_SMEM);

    init_kernel<<<1, 32>>>(out, target, mask);
    cvt_kernel<<<1184, 256>>>(feats, W);

    dim3 ggrid(NTILES, M_TOT / 128);   // 20 x 256
    gemm_tc_kernel<<<ggrid, 256, GEMM_SMEM>>>(bias);

    tg_kernel<<<M_TOT / 8, 256>>>(feats, W, bias, target, mask);

    scan_kernel<<<BATCH, 64>>>(mask, out);
}